// round 3
// baseline (speedup 1.0000x reference)
#include <cuda_runtime.h>
#include <cuda_bf16.h>

#define NN 100000
#define NE 1600000
#define D  128

// ---------------- scratch (device globals; allocation-free) ----------------
__device__ float g_bufA[NN * D];      // holds hs = h * norm_src (gather source)
__device__ float g_bufB[NN * D];      // holds aggregated m * norm_dst (GEMM input)
__device__ float g_norm_src[NN];
__device__ float g_norm_dst[NN];
__device__ int   g_deg_out[NN];
__device__ int   g_deg_in[NN];
__device__ int   g_row_ptr[NN + 1];
__device__ int   g_cursor[NN];
__device__ int   g_col[NE];

// ---------------- graph preprocessing ----------------
__global__ void k_init_deg() {
    int i = blockIdx.x * blockDim.x + threadIdx.x;
    if (i < NN) { g_deg_out[i] = 1; g_deg_in[i] = 1; }   // self-loop contributes 1
}

__global__ void k_count(const int* __restrict__ src, const int* __restrict__ dst) {
    int e = blockIdx.x * blockDim.x + threadIdx.x;
    if (e < NE) {
        atomicAdd(&g_deg_out[src[e]], 1);
        atomicAdd(&g_deg_in[dst[e]], 1);
    }
}

__global__ void k_norm() {
    int i = blockIdx.x * blockDim.x + threadIdx.x;
    if (i < NN) {
        g_norm_src[i] = rsqrtf((float)g_deg_out[i]);
        g_norm_dst[i] = rsqrtf((float)g_deg_in[i]);
    }
}

// single-block exclusive scan of real (non-self-loop) in-degrees -> row_ptr
__global__ void k_scan() {
    const int T = 1024;
    int t = threadIdx.x;
    const int chunk = (NN + T - 1) / T;   // 98
    int lo = t * chunk;
    int hi = min(lo + chunk, NN);
    int s = 0;
    for (int i = lo; i < hi; i++) s += g_deg_in[i] - 1;
    __shared__ int sh[T];
    sh[t] = s;
    __syncthreads();
    for (int off = 1; off < T; off <<= 1) {
        int v = (t >= off) ? sh[t - off] : 0;
        __syncthreads();
        sh[t] += v;
        __syncthreads();
    }
    int run = (t == 0) ? 0 : sh[t - 1];
    for (int i = lo; i < hi; i++) {
        g_row_ptr[i] = run;
        g_cursor[i]  = run;
        run += g_deg_in[i] - 1;
    }
    if (t == T - 1) g_row_ptr[NN] = run;  // == NE
}

__global__ void k_fill(const int* __restrict__ src, const int* __restrict__ dst) {
    int e = blockIdx.x * blockDim.x + threadIdx.x;
    if (e < NE) {
        int p = atomicAdd(&g_cursor[dst[e]], 1);
        g_col[p] = src[e];
    }
}

// ---------------- layer-0 input scale: bufA = input * norm_src ----------------
__global__ void k_scale0(const float* __restrict__ in) {
    int idx = blockIdx.x * blockDim.x + threadIdx.x;   // float4 index
    if (idx < NN * (D / 4)) {
        int row = idx >> 5;                            // / (D/4)
        float s = g_norm_src[row];
        float4 v = ((const float4*)in)[idx];
        v.x *= s; v.y *= s; v.z *= s; v.w *= s;
        ((float4*)g_bufA)[idx] = v;
    }
}

// ---------------- aggregation: warp per node, gather-sum from bufA -> bufB ----
__global__ __launch_bounds__(256) void k_agg() {
    int gw   = (blockIdx.x * blockDim.x + threadIdx.x) >> 5;
    int lane = threadIdx.x & 31;
    if (gw >= NN) return;
    const float4* __restrict__ h4 = (const float4*)g_bufA;
    int base = gw * (D / 4) + lane;
    float4 acc = h4[base];                 // self-loop term
    int s = g_row_ptr[gw];
    int e = g_row_ptr[gw + 1];
    int i = s;
    for (; i + 4 <= e; i += 4) {
        int c0 = g_col[i], c1 = g_col[i + 1], c2 = g_col[i + 2], c3 = g_col[i + 3];
        float4 v0 = h4[c0 * 32 + lane];
        float4 v1 = h4[c1 * 32 + lane];
        float4 v2 = h4[c2 * 32 + lane];
        float4 v3 = h4[c3 * 32 + lane];
        acc.x += (v0.x + v1.x) + (v2.x + v3.x);
        acc.y += (v0.y + v1.y) + (v2.y + v3.y);
        acc.z += (v0.z + v1.z) + (v2.z + v3.z);
        acc.w += (v0.w + v1.w) + (v2.w + v3.w);
    }
    for (; i < e; i++) {
        int c = g_col[i];
        float4 v = h4[c * 32 + lane];
        acc.x += v.x; acc.y += v.y; acc.z += v.z; acc.w += v.w;
    }
    float nd = g_norm_dst[gw];             // fold norm_dst here
    acc.x *= nd; acc.y *= nd; acc.z *= nd; acc.w *= nd;
    ((float4*)g_bufB)[base] = acc;
}

// ---------------- GEMM: out = (bufB @ W + b), optional relu*norm_src fused ----
// 64-row tiles, W + padded A-tile in dynamic smem, 4x8 register blocking.
__global__ __launch_bounds__(256, 2) void k_gemm(
    const float* __restrict__ W,       // [128,128] row-major (k,n)
    const float* __restrict__ bias,    // [128]
    int relu_scale,                    // 1: relu then * norm_src; 0: plain
    float* __restrict__ extout)        // nullptr -> write g_bufA
{
    extern __shared__ float smem[];
    float* sW = smem;                  // 128*128
    float* sA = smem + D * D;          // 64 rows * 132 (padded)
    float* gout = extout ? extout : g_bufA;

    int tid = threadIdx.x;

    // stage W (64KB)
    const float4* W4 = (const float4*)W;
    float4* sW4 = (float4*)sW;
#pragma unroll
    for (int i = 0; i < 16; i++) sW4[tid + i * 256] = W4[tid + i * 256];

    // stage A tile (64 rows x 128, padded stride 132)
    int r0 = blockIdx.x * 64;
    const float4* A4 = (const float4*)g_bufB;
#pragma unroll
    for (int i = 0; i < 8; i++) {
        int idx = tid + i * 256;       // float4 index in tile
        int row = idx >> 5;
        int c4  = idx & 31;
        float4 v = make_float4(0.f, 0.f, 0.f, 0.f);
        int gr = r0 + row;
        if (gr < NN) v = A4[gr * 32 + c4];
        *(float4*)&sA[row * 132 + c4 * 4] = v;   // 132*4B = 33*16B -> 16B aligned
    }
    __syncthreads();

    int cg = tid & 15;                 // column group: 8 cols each
    int rg = tid >> 4;                 // row group: 4 rows each
    int n0 = cg * 8;
    int rr = rg * 4;

    float acc[4][8];
#pragma unroll
    for (int i = 0; i < 4; i++)
#pragma unroll
        for (int j = 0; j < 8; j++) acc[i][j] = 0.f;

    const float* a0p = &sA[rr * 132];
#pragma unroll 8
    for (int k = 0; k < D; k++) {
        float aa0 = a0p[k];
        float aa1 = a0p[132 + k];
        float aa2 = a0p[264 + k];
        float aa3 = a0p[396 + k];
        float4 b0 = *(const float4*)&sW[k * D + n0];
        float4 b1 = *(const float4*)&sW[k * D + n0 + 4];
        float bb[8] = { b0.x, b0.y, b0.z, b0.w, b1.x, b1.y, b1.z, b1.w };
        float aa[4] = { aa0, aa1, aa2, aa3 };
#pragma unroll
        for (int i = 0; i < 4; i++)
#pragma unroll
            for (int j = 0; j < 8; j++) acc[i][j] += aa[i] * bb[j];
    }

    float bv[8];
#pragma unroll
    for (int j = 0; j < 8; j++) bv[j] = bias[n0 + j];

#pragma unroll
    for (int i = 0; i < 4; i++) {
        int gr = r0 + rr + i;
        if (gr < NN) {
            float s = relu_scale ? g_norm_src[gr] : 1.0f;
            float o[8];
#pragma unroll
            for (int j = 0; j < 8; j++) {
                float v = acc[i][j] + bv[j];
                if (relu_scale) v = fmaxf(v, 0.f) * s;  // relu(x)*s == relu(x*s), s>0
                o[j] = v;
            }
            float4* op = (float4*)&gout[gr * D + n0];
            op[0] = make_float4(o[0], o[1], o[2], o[3]);
            op[1] = make_float4(o[4], o[5], o[6], o[7]);
        }
    }
}

// ---------------- launch ----------------
extern "C" void kernel_launch(void* const* d_in, const int* in_sizes, int n_in,
                              void* d_out, int out_size) {
    const float* inputs = (const float*)d_in[0];   // [N,128]
    const float* Ws     = (const float*)d_in[1];   // [3,128,128]
    const float* bs     = (const float*)d_in[2];   // [3,128]
    const int*   src    = (const int*)d_in[3];     // [E]
    const int*   dst    = (const int*)d_in[4];     // [E]
    float*       out    = (float*)d_out;           // [N,128]

    const int smem_bytes = (D * D + 64 * 132) * (int)sizeof(float);  // 99328
    cudaFuncSetAttribute(k_gemm, cudaFuncAttributeMaxDynamicSharedMemorySize, smem_bytes);

    // graph preprocessing (every call; deterministic sums, int atomics only)
    k_init_deg<<<(NN + 255) / 256, 256>>>();
    k_count<<<(NE + 255) / 256, 256>>>(src, dst);
    k_norm<<<(NN + 255) / 256, 256>>>();
    k_scan<<<1, 1024>>>();
    k_fill<<<(NE + 255) / 256, 256>>>(src, dst);

    // layer 0 input scale
    k_scale0<<<(NN * (D / 4) + 255) / 256, 256>>>(inputs);

    const int agg_blocks  = (NN * 32 + 255) / 256;   // warp per node
    const int gemm_blocks = (NN + 63) / 64;

    for (int l = 0; l < 3; l++) {
        k_agg<<<agg_blocks, 256>>>();
        k_gemm<<<gemm_blocks, 256, smem_bytes>>>(
            Ws + l * D * D, bs + l * D,
            (l < 2) ? 1 : 0,
            (l == 2) ? out : nullptr);
    }
}

// round 7
// speedup vs baseline: 1.2254x; 1.2254x over previous
#include <cuda_runtime.h>
#include <cuda_bf16.h>

#define NN 100000
#define NE 1600000
#define D  128

// ---------------- scratch (device globals; allocation-free) ----------------
__device__ float g_bufA[NN * D];      // holds hs = h * norm_src (gather source)
__device__ float g_bufB[NN * D];      // holds aggregated m * norm_dst (GEMM input)
__device__ float g_norm_src[NN];
__device__ float g_norm_dst[NN];
__device__ int   g_deg_out[NN];
__device__ int   g_deg_in[NN];
__device__ int   g_row_start[NN];     // slot base per node (arbitrary order, disjoint)
__device__ int   g_cursor[NN];
__device__ int   g_col[NE];
__device__ int   g_alloc;

// ---------------- graph preprocessing ----------------
__global__ void k_init_deg() {
    int i = blockIdx.x * blockDim.x + threadIdx.x;
    if (i < NN) { g_deg_out[i] = 1; g_deg_in[i] = 1; }   // self-loop contributes 1
    if (i == 0) g_alloc = 0;
}

__global__ void k_count(const int* __restrict__ src, const int* __restrict__ dst) {
    int e = blockIdx.x * blockDim.x + threadIdx.x;
    if (e < NE) {
        atomicAdd(&g_deg_out[src[e]], 1);
        atomicAdd(&g_deg_in[dst[e]], 1);
    }
}

// norms + warp-aggregated slot allocation (replaces the 161us serial scan)
__global__ void k_norm_alloc() {
    int i = blockIdx.x * blockDim.x + threadIdx.x;
    int lane = threadIdx.x & 31;
    bool valid = i < NN;
    int din  = valid ? g_deg_in[i]  : 1;
    int dout = valid ? g_deg_out[i] : 1;
    if (valid) {
        g_norm_src[i] = rsqrtf((float)dout);
        g_norm_dst[i] = rsqrtf((float)din);
    }
    int d = din - 1;                       // real (non-self) in-degree
    int p = d;                             // inclusive warp scan
#pragma unroll
    for (int off = 1; off < 32; off <<= 1) {
        int v = __shfl_up_sync(0xffffffffu, p, off);
        if (lane >= off) p += v;
    }
    int total = __shfl_sync(0xffffffffu, p, 31);
    int base = 0;
    if (lane == 31) base = atomicAdd(&g_alloc, total);
    base = __shfl_sync(0xffffffffu, base, 31);
    int start = base + p - d;              // exclusive prefix within warp
    if (valid) { g_row_start[i] = start; g_cursor[i] = start; }
}

__global__ void k_fill(const int* __restrict__ src, const int* __restrict__ dst) {
    int e = blockIdx.x * blockDim.x + threadIdx.x;
    if (e < NE) {
        int p = atomicAdd(&g_cursor[dst[e]], 1);
        g_col[p] = src[e];
    }
}

// ---------------- layer-0 input scale: bufA = input * norm_src ----------------
__global__ void k_scale0(const float* __restrict__ in) {
    int idx = blockIdx.x * blockDim.x + threadIdx.x;   // float4 index
    if (idx < NN * (D / 4)) {
        int row = idx >> 5;                            // / (D/4)
        float s = g_norm_src[row];
        float4 v = ((const float4*)in)[idx];
        v.x *= s; v.y *= s; v.z *= s; v.w *= s;
        ((float4*)g_bufA)[idx] = v;
    }
}

// ---------------- aggregation: warp per node, gather-sum from bufA -> bufB ----
__global__ __launch_bounds__(256) void k_agg() {
    int gw   = (blockIdx.x * blockDim.x + threadIdx.x) >> 5;
    int lane = threadIdx.x & 31;
    if (gw >= NN) return;
    const float4* __restrict__ h4 = (const float4*)g_bufA;
    int base = gw * (D / 4) + lane;
    float4 acc = h4[base];                 // self-loop term
    int s = g_row_start[gw];
    int e = s + g_deg_in[gw] - 1;
    int i = s;
    for (; i + 4 <= e; i += 4) {
        int c0 = g_col[i], c1 = g_col[i + 1], c2 = g_col[i + 2], c3 = g_col[i + 3];
        float4 v0 = h4[c0 * 32 + lane];
        float4 v1 = h4[c1 * 32 + lane];
        float4 v2 = h4[c2 * 32 + lane];
        float4 v3 = h4[c3 * 32 + lane];
        acc.x += (v0.x + v1.x) + (v2.x + v3.x);
        acc.y += (v0.y + v1.y) + (v2.y + v3.y);
        acc.z += (v0.z + v1.z) + (v2.z + v3.z);
        acc.w += (v0.w + v1.w) + (v2.w + v3.w);
    }
    for (; i < e; i++) {
        int c = g_col[i];
        float4 v = h4[c * 32 + lane];
        acc.x += v.x; acc.y += v.y; acc.z += v.z; acc.w += v.w;
    }
    float nd = g_norm_dst[gw];             // fold norm_dst here
    acc.x *= nd; acc.y *= nd; acc.z *= nd; acc.w *= nd;
    ((float4*)g_bufB)[base] = acc;
}

// ---------------- packed f32x2 helpers ----------------
__device__ __forceinline__ unsigned long long pack2(float lo, float hi) {
    unsigned long long r;
    asm("mov.b64 %0, {%1, %2};" : "=l"(r) : "f"(lo), "f"(hi));
    return r;
}
__device__ __forceinline__ void unpack2(unsigned long long v, float& lo, float& hi) {
    asm("mov.b64 {%0, %1}, %2;" : "=f"(lo), "=f"(hi) : "l"(v));
}
__device__ __forceinline__ unsigned long long fma2(unsigned long long a,
                                                   unsigned long long b,
                                                   unsigned long long c) {
    unsigned long long d;
    asm("fma.rn.f32x2 %0, %1, %2, %3;" : "=l"(d) : "l"(a), "l"(b), "l"(c));
    return d;
}

// ---------------- GEMM: out = (bufB @ W + b), optional relu*norm_src fused ----
// 64-row tiles, W + padded A-tile in dynamic smem, 4x8 register blocking,
// accumulation in packed f32x2 (FFMA2).
__global__ __launch_bounds__(256, 2) void k_gemm(
    const float* __restrict__ W,       // [128,128] row-major (k,n)
    const float* __restrict__ bias,    // [128]
    int relu_scale,                    // 1: relu then * norm_src; 0: plain
    float* __restrict__ extout)        // nullptr -> write g_bufA
{
    extern __shared__ float smem[];
    float* sW = smem;                  // 128*128
    float* sA = smem + D * D;          // 64 rows * 132 (padded)
    float* gout = extout ? extout : g_bufA;

    int tid = threadIdx.x;

    // stage W (64KB)
    const float4* W4 = (const float4*)W;
    float4* sW4 = (float4*)sW;
#pragma unroll
    for (int i = 0; i < 16; i++) sW4[tid + i * 256] = W4[tid + i * 256];

    // stage A tile (64 rows x 128, padded stride 132)
    int r0 = blockIdx.x * 64;
    const float4* A4 = (const float4*)g_bufB;
#pragma unroll
    for (int i = 0; i < 8; i++) {
        int idx = tid + i * 256;       // float4 index in tile
        int row = idx >> 5;
        int c4  = idx & 31;
        float4 v = make_float4(0.f, 0.f, 0.f, 0.f);
        int gr = r0 + row;
        if (gr < NN) v = A4[gr * 32 + c4];
        *(float4*)&sA[row * 132 + c4 * 4] = v;   // 16B aligned (132*4B = 33*16B)
    }
    __syncthreads();

    int cg = tid & 15;                 // column group: 8 cols each
    int rg = tid >> 4;                 // row group: 4 rows each
    int n0 = cg * 8;
    int rr = rg * 4;

    // accumulators: 4 rows x 4 f32x2 pairs (8 cols); init with bias pairs
    unsigned long long acc2[4][4];
    {
        const ulonglong2* bp = (const ulonglong2*)&bias[n0];   // 32B aligned
        ulonglong2 bq0 = bp[0], bq1 = bp[1];
        unsigned long long binit[4] = { bq0.x, bq0.y, bq1.x, bq1.y };
#pragma unroll
        for (int i = 0; i < 4; i++)
#pragma unroll
            for (int j = 0; j < 4; j++) acc2[i][j] = binit[j];
    }

    const float* a0p = &sA[rr * 132];
#pragma unroll 8
    for (int k = 0; k < D; k++) {
        unsigned long long a2[4];
        a2[0] = pack2(a0p[k],        a0p[k]);
        a2[1] = pack2(a0p[132 + k],  a0p[132 + k]);
        a2[2] = pack2(a0p[264 + k],  a0p[264 + k]);
        a2[3] = pack2(a0p[396 + k],  a0p[396 + k]);
        const ulonglong2* wp = (const ulonglong2*)&sW[k * D + n0];
        ulonglong2 w0 = wp[0], w1 = wp[1];
        unsigned long long b2[4] = { w0.x, w0.y, w1.x, w1.y };
#pragma unroll
        for (int i = 0; i < 4; i++)
#pragma unroll
            for (int j = 0; j < 4; j++)
                acc2[i][j] = fma2(a2[i], b2[j], acc2[i][j]);
    }

#pragma unroll
    for (int i = 0; i < 4; i++) {
        int gr = r0 + rr + i;
        if (gr < NN) {
            float s = relu_scale ? g_norm_src[gr] : 1.0f;
            float o[8];
#pragma unroll
            for (int j = 0; j < 4; j++) unpack2(acc2[i][j], o[2 * j], o[2 * j + 1]);
            if (relu_scale) {
#pragma unroll
                for (int j = 0; j < 8; j++) o[j] = fmaxf(o[j], 0.f) * s;  // relu(x)*s == relu(x*s), s>0
            }
            float4* op = (float4*)&gout[gr * D + n0];
            op[0] = make_float4(o[0], o[1], o[2], o[3]);
            op[1] = make_float4(o[4], o[5], o[6], o[7]);
        }
    }
}

// ---------------- launch ----------------
extern "C" void kernel_launch(void* const* d_in, const int* in_sizes, int n_in,
                              void* d_out, int out_size) {
    const float* inputs = (const float*)d_in[0];   // [N,128]
    const float* Ws     = (const float*)d_in[1];   // [3,128,128]
    const float* bs     = (const float*)d_in[2];   // [3,128]
    const int*   src    = (const int*)d_in[3];     // [E]
    const int*   dst    = (const int*)d_in[4];     // [E]
    float*       out    = (float*)d_out;           // [N,128]

    const int smem_bytes = (D * D + 64 * 132) * (int)sizeof(float);  // 99328
    cudaFuncSetAttribute(k_gemm, cudaFuncAttributeMaxDynamicSharedMemorySize, smem_bytes);

    // graph preprocessing (every call; int atomics only)
    k_init_deg<<<(NN + 255) / 256, 256>>>();
    k_count<<<(NE + 255) / 256, 256>>>(src, dst);
    k_norm_alloc<<<(NN + 255) / 256, 256>>>();
    k_fill<<<(NE + 255) / 256, 256>>>(src, dst);

    // layer 0 input scale
    k_scale0<<<(NN * (D / 4) + 255) / 256, 256>>>(inputs);

    const int agg_blocks  = (NN * 32 + 255) / 256;   // warp per node
    const int gemm_blocks = (NN + 63) / 64;

    for (int l = 0; l < 3; l++) {
        k_agg<<<agg_blocks, 256>>>();
        k_gemm<<<gemm_blocks, 256, smem_bytes>>>(
            Ws + l * D * D, bs + l * D,
            (l < 2) ? 1 : 0,
            (l == 2) ? out : nullptr);
    }
}

// round 9
// speedup vs baseline: 2.0916x; 1.7069x over previous
#include <cuda_runtime.h>
#include <cuda_fp16.h>
#include <cstdint>

#define NN 100000
#define NE 1600000
#define D  128
#define NTILES ((NN + 127) / 128)   // 782
#define PW 136                       // padded W row (halves): 272B -> conflict-free ldmatrix

// ---------------- scratch (device globals; allocation-free) ----------------
__device__ float  g_bufA[NN * D];     // f32 activations (gather source / gemm out)
__device__ __half g_Ah[NN * D];       // gemm input, fp16 hi
__device__ __half g_Al[NN * D];       // gemm input, fp16 lo
__device__ float  g_norm_src[NN];
__device__ float  g_norm_dst[NN];
__device__ int    g_deg_out[NN];
__device__ int    g_deg_in[NN];
__device__ int    g_row_start[NN];
__device__ int    g_cursor[NN];
__device__ int    g_col[NE];
__device__ int    g_alloc;
__device__ __half g_Whp[3 * D * PW];  // W^T fp16-hi, padded rows
__device__ __half g_Wlp[3 * D * PW];  // W^T fp16-lo, padded rows

// ---------------- asm helpers ----------------
__device__ __forceinline__ uint32_t smem_u32(const void* p) {
    uint32_t a;
    asm("{ .reg .u64 t; cvta.to.shared.u64 t, %1; cvt.u32.u64 %0, t; }" : "=r"(a) : "l"(p));
    return a;
}

#define LDSM_X4(r, addr) \
    asm volatile("ldmatrix.sync.aligned.m8n8.x4.shared.b16 {%0,%1,%2,%3}, [%4];" \
        : "=r"((r)[0]), "=r"((r)[1]), "=r"((r)[2]), "=r"((r)[3]) : "r"(addr))

#define MMA16816(d, a, b0, b1) \
    asm volatile("mma.sync.aligned.m16n8k16.row.col.f32.f16.f16.f32 " \
        "{%0,%1,%2,%3}, {%4,%5,%6,%7}, {%8,%9}, {%0,%1,%2,%3};" \
        : "+f"((d)[0]), "+f"((d)[1]), "+f"((d)[2]), "+f"((d)[3]) \
        : "r"((a)[0]), "r"((a)[1]), "r"((a)[2]), "r"((a)[3]), "r"(b0), "r"(b1))

// ---------------- graph preprocessing ----------------
__global__ void k_init_deg() {
    int i = blockIdx.x * blockDim.x + threadIdx.x;
    if (i < NN) { g_deg_out[i] = 1; g_deg_in[i] = 1; }   // self-loop contributes 1
    if (i == 0) g_alloc = 0;
}

__global__ void k_count(const int* __restrict__ src, const int* __restrict__ dst) {
    int e = blockIdx.x * blockDim.x + threadIdx.x;
    if (e < NE) {
        atomicAdd(&g_deg_out[src[e]], 1);
        atomicAdd(&g_deg_in[dst[e]], 1);
    }
}

__global__ void k_norm_alloc() {
    int i = blockIdx.x * blockDim.x + threadIdx.x;
    int lane = threadIdx.x & 31;
    bool valid = i < NN;
    int din  = valid ? g_deg_in[i]  : 1;
    int dout = valid ? g_deg_out[i] : 1;
    if (valid) {
        g_norm_src[i] = rsqrtf((float)dout);
        g_norm_dst[i] = rsqrtf((float)din);
    }
    int d = din - 1;
    int p = d;
#pragma unroll
    for (int off = 1; off < 32; off <<= 1) {
        int v = __shfl_up_sync(0xffffffffu, p, off);
        if (lane >= off) p += v;
    }
    int total = __shfl_sync(0xffffffffu, p, 31);
    int base = 0;
    if (lane == 31) base = atomicAdd(&g_alloc, total);
    base = __shfl_sync(0xffffffffu, base, 31);
    int start = base + p - d;
    if (valid) { g_row_start[i] = start; g_cursor[i] = start; }
}

__global__ void k_fill(const int* __restrict__ src, const int* __restrict__ dst) {
    int e = blockIdx.x * blockDim.x + threadIdx.x;
    if (e < NE) {
        int p = atomicAdd(&g_cursor[dst[e]], 1);
        g_col[p] = src[e];
    }
}

// ---------------- W prep: W^T -> fp16 hi/lo, padded rows ----------------
__global__ void k_wprep(const float* __restrict__ Ws) {
    int idx = blockIdx.x * blockDim.x + threadIdx.x;
    if (idx >= 3 * D * D) return;
    int l = idx >> 14;
    int r = idx & 16383;
    int n = r >> 7;
    int k = r & 127;
    float v = Ws[(l << 14) + (k << 7) + n];          // W[l][k][n] = Wt[n][k]
    __half hi = __float2half_rn(v);
    __half lo = __float2half_rn(v - __half2float(hi));
    int o = (l * D + n) * PW + k;
    g_Whp[o] = hi;
    g_Wlp[o] = lo;
    if (k < PW - D) {                                // zero the pad
        g_Whp[(l * D + n) * PW + D + k] = __float2half_rn(0.f);
        g_Wlp[(l * D + n) * PW + D + k] = __float2half_rn(0.f);
    }
}

// ---------------- layer-0 input scale: bufA = input * norm_src ----------------
__global__ void k_scale0(const float* __restrict__ in) {
    int idx = blockIdx.x * blockDim.x + threadIdx.x;
    if (idx < NN * (D / 4)) {
        int row = idx >> 5;
        float s = g_norm_src[row];
        float4 v = ((const float4*)in)[idx];
        v.x *= s; v.y *= s; v.z *= s; v.w *= s;
        ((float4*)g_bufA)[idx] = v;
    }
}

// ---------------- aggregation: warp per node; epilogue emits fp16 hi/lo ------
__global__ __launch_bounds__(256) void k_agg() {
    int gw   = (blockIdx.x * blockDim.x + threadIdx.x) >> 5;
    int lane = threadIdx.x & 31;
    if (gw >= NN) return;
    const float4* __restrict__ h4 = (const float4*)g_bufA;
    int base = gw * (D / 4) + lane;
    float4 acc = h4[base];                 // self-loop term
    int s = g_row_start[gw];
    int e = s + g_deg_in[gw] - 1;
    int i = s;
    for (; i + 4 <= e; i += 4) {
        int c0 = g_col[i], c1 = g_col[i + 1], c2 = g_col[i + 2], c3 = g_col[i + 3];
        float4 v0 = h4[c0 * 32 + lane];
        float4 v1 = h4[c1 * 32 + lane];
        float4 v2 = h4[c2 * 32 + lane];
        float4 v3 = h4[c3 * 32 + lane];
        acc.x += (v0.x + v1.x) + (v2.x + v3.x);
        acc.y += (v0.y + v1.y) + (v2.y + v3.y);
        acc.z += (v0.z + v1.z) + (v2.z + v3.z);
        acc.w += (v0.w + v1.w) + (v2.w + v3.w);
    }
    for (; i < e; i++) {
        int c = g_col[i];
        float4 v = h4[c * 32 + lane];
        acc.x += v.x; acc.y += v.y; acc.z += v.z; acc.w += v.w;
    }
    float nd = g_norm_dst[gw];             // fold norm_dst here
    acc.x *= nd; acc.y *= nd; acc.z *= nd; acc.w *= nd;

    // fp16 hi/lo split (3-term GEMM input)
    float av[4] = { acc.x, acc.y, acc.z, acc.w };
    __half hh[4], ll[4];
#pragma unroll
    for (int j = 0; j < 4; j++) {
        hh[j] = __float2half_rn(av[j]);
        ll[j] = __float2half_rn(av[j] - __half2float(hh[j]));
    }
    // 4 halves = 8B per store; element index gw*128 + 4*lane (8B-aligned)
    *(uint2*)(&g_Ah[gw * D + 4 * lane]) = *(const uint2*)hh;
    *(uint2*)(&g_Al[gw * D + 4 * lane]) = *(const uint2*)ll;
}

// ---------------- HMMA GEMM: gout = A @ W + b (persistent) --------------------
// Block 256 thr (8 warps): warp (wm,wc) owns 32 rows x 64 cols of a 128x128 tile.
// B (W^T hi/lo) staged in padded smem, fragments via ldmatrix.x4 (conflict-free);
// A fragments loaded directly from gmem (L2-resident). 3-term fp16 MMA.
__global__ __launch_bounds__(256, 2) void k_gemm_mma(
    int layer, const float* __restrict__ bias,
    int relu_scale, float* __restrict__ extout)
{
    extern __shared__ __half sm[];              // [2][128*136] halves
    __shared__ float s_bias[D];
    float* gout = extout ? extout : g_bufA;

    int tid  = threadIdx.x;
    int wid  = tid >> 5;
    int lane = tid & 31;
    int wm   = wid & 3;        // row 32-group
    int wc   = wid >> 2;       // col 64-half
    int q    = lane & 3;
    int tr   = lane >> 2;

    // stage W^T hi/lo (padded layout identical in gmem -> bulk int4 copy)
    {
        const int4* srcH = (const int4*)(g_Whp + layer * D * PW);
        const int4* srcL = (const int4*)(g_Wlp + layer * D * PW);
        int4* dstH = (int4*)sm;
        int4* dstL = (int4*)(sm + D * PW);
        const int CH = D * PW * 2 / 16;   // 2176 int4 per array
        for (int i = tid; i < CH; i += 256) { dstH[i] = srcH[i]; dstL[i] = srcL[i]; }
    }
    if (tid < D) s_bias[tid] = bias[tid];
    __syncthreads();

    uint32_t sH = smem_u32(sm);
    uint32_t sL = sH + D * PW * 2;
    // ldmatrix per-thread row address (byte): matrix id m = lane/8, row r = lane%8
    int lm_m = lane >> 3;
    int lm_r = lane & 7;
    uint32_t lm_off = (uint32_t)(8 * (lm_m >> 1) + lm_r) * (PW * 2) + (uint32_t)(lm_m & 1) * 16;

    const __half* __restrict__ Ah = g_Ah;
    const __half* __restrict__ Al = g_Al;

    for (int t = blockIdx.x; t < NTILES; t += gridDim.x) {
        int r0 = t * 128;
        bool full = (r0 + 128 <= NN);
        int rbase0 = r0 + wm * 32 + tr;       // mset 0 rows: rbase0, rbase0+8
        int rbase1 = rbase0 + 16;             // mset 1 rows: rbase1, rbase1+8

        float acc[2][8][4];
#pragma unroll
        for (int m = 0; m < 2; m++)
#pragma unroll
            for (int j = 0; j < 8; j++)
#pragma unroll
                for (int c = 0; c < 4; c++) acc[m][j][c] = 0.f;

        for (int s = 0; s < 8; s++) {
            int kb = s * 16 + q * 2;          // element offset within row
            uint32_t aH[2][4], aL[2][4];
#pragma unroll
            for (int m = 0; m < 2; m++) {
                int ra = (m ? rbase1 : rbase0);
                int rb = ra + 8;
                size_t oa = (size_t)ra * D + kb;
                size_t ob = (size_t)rb * D + kb;
                if (full || rb < NN) {
                    aH[m][0] = *(const uint32_t*)(Ah + oa);
                    aH[m][2] = *(const uint32_t*)(Ah + oa + 8);
                    aH[m][1] = *(const uint32_t*)(Ah + ob);
                    aH[m][3] = *(const uint32_t*)(Ah + ob + 8);
                    aL[m][0] = *(const uint32_t*)(Al + oa);
                    aL[m][2] = *(const uint32_t*)(Al + oa + 8);
                    aL[m][1] = *(const uint32_t*)(Al + ob);
                    aL[m][3] = *(const uint32_t*)(Al + ob + 8);
                } else {
                    bool va = ra < NN;
                    aH[m][0] = va ? *(const uint32_t*)(Ah + oa) : 0u;
                    aH[m][2] = va ? *(const uint32_t*)(Ah + oa + 8) : 0u;
                    aL[m][0] = va ? *(const uint32_t*)(Al + oa) : 0u;
                    aL[m][2] = va ? *(const uint32_t*)(Al + oa + 8) : 0u;
                    aH[m][1] = 0u; aH[m][3] = 0u; aL[m][1] = 0u; aL[m][3] = 0u;
                }
            }
#pragma unroll
            for (int p = 0; p < 4; p++) {     // ntile pairs (j = 2p, 2p+1)
                uint32_t nb = (uint32_t)(wc * 64 + p * 16) * (PW * 2) + (uint32_t)s * 32;
                uint32_t bH[4], bL[4];
                LDSM_X4(bH, sH + nb + lm_off);
                LDSM_X4(bL, sL + nb + lm_off);
#pragma unroll
                for (int m = 0; m < 2; m++) {
#pragma unroll
                    for (int u = 0; u < 2; u++) {
                        int j = 2 * p + u;
                        MMA16816(acc[m][j], aH[m], bH[2 * u], bH[2 * u + 1]);   // Ah*Bh
                        MMA16816(acc[m][j], aH[m], bL[2 * u], bL[2 * u + 1]);   // Ah*Bl
                        MMA16816(acc[m][j], aL[m], bH[2 * u], bH[2 * u + 1]);   // Al*Bh
                    }
                }
            }
        }

        // epilogue: bias + (relu * norm_src) fused; c0,c1 -> row, c2,c3 -> row+8
#pragma unroll
        for (int m = 0; m < 2; m++) {
            int ra = (m ? rbase1 : rbase0);
            int rb = ra + 8;
            float nsa = 1.f, nsb = 1.f;
            if (relu_scale) {
                if (ra < NN) nsa = g_norm_src[ra];
                if (rb < NN) nsb = g_norm_src[rb];
            }
#pragma unroll
            for (int j = 0; j < 8; j++) {
                int col = wc * 64 + j * 8 + q * 2;
                float b0 = s_bias[col], b1 = s_bias[col + 1];
                float v0 = acc[m][j][0] + b0, v1 = acc[m][j][1] + b1;
                float v2 = acc[m][j][2] + b0, v3 = acc[m][j][3] + b1;
                if (relu_scale) {
                    v0 = fmaxf(v0, 0.f) * nsa; v1 = fmaxf(v1, 0.f) * nsa;
                    v2 = fmaxf(v2, 0.f) * nsb; v3 = fmaxf(v3, 0.f) * nsb;
                }
                if (ra < NN) *(float2*)(gout + (size_t)ra * D + col) = make_float2(v0, v1);
                if (rb < NN) *(float2*)(gout + (size_t)rb * D + col) = make_float2(v2, v3);
            }
        }
    }
}

// ---------------- launch ----------------
extern "C" void kernel_launch(void* const* d_in, const int* in_sizes, int n_in,
                              void* d_out, int out_size) {
    const float* inputs = (const float*)d_in[0];   // [N,128]
    const float* Ws     = (const float*)d_in[1];   // [3,128,128]
    const float* bs     = (const float*)d_in[2];   // [3,128]
    const int*   src    = (const int*)d_in[3];     // [E]
    const int*   dst    = (const int*)d_in[4];     // [E]
    float*       out    = (float*)d_out;           // [N,128]

    const int gemm_smem = 2 * D * PW * (int)sizeof(__half);   // 69632
    cudaFuncSetAttribute(k_gemm_mma, cudaFuncAttributeMaxDynamicSharedMemorySize, gemm_smem);

    // graph preprocessing (every call; int atomics only)
    k_init_deg<<<(NN + 255) / 256, 256>>>();
    k_count<<<(NE + 255) / 256, 256>>>(src, dst);
    k_norm_alloc<<<(NN + 255) / 256, 256>>>();
    k_fill<<<(NE + 255) / 256, 256>>>(src, dst);

    // W split + layer-0 input scale
    k_wprep<<<(3 * D * D + 255) / 256, 256>>>(Ws);
    k_scale0<<<(NN * (D / 4) + 255) / 256, 256>>>(inputs);

    const int agg_blocks = (NN * 32 + 255) / 256;   // warp per node

    for (int l = 0; l < 3; l++) {
        k_agg<<<agg_blocks, 256>>>();
        k_gemm_mma<<<296, 256, gemm_smem>>>(
            l, bs + l * D,
            (l < 2) ? 1 : 0,
            (l == 2) ? out : nullptr);
    }
}

// round 12
// speedup vs baseline: 2.2678x; 1.0842x over previous
#include <cuda_runtime.h>
#include <cuda_fp16.h>
#include <cstdint>

#define NN 100000
#define NE 1600000
#define D  128
#define NTILES ((NN + 127) / 128)   // 782
#define PW 136                       // padded W row (halves): 272B -> conflict-free ldmatrix

// ---------------- scratch (device globals; allocation-free) ----------------
__device__ __half g_hs[NN * D];       // gather source: h * norm_src, fp16
__device__ __half g_Ah[NN * D];       // gemm input (aggregated), fp16 hi
__device__ __half g_Al[NN * D];       // gemm input (aggregated), fp16 lo
__device__ float  g_norm_src[NN];
__device__ float  g_norm_dst[NN];
__device__ int    g_deg_out[NN];
__device__ int    g_deg_in[NN];
__device__ int    g_row_start[NN];
__device__ int    g_cursor[NN];
__device__ int    g_col[NE];
__device__ int    g_alloc;
__device__ __half g_Whp[3 * D * PW];  // W^T fp16-hi, padded rows
__device__ __half g_Wlp[3 * D * PW];  // W^T fp16-lo, padded rows

// ---------------- helpers ----------------
__device__ __forceinline__ uint32_t smem_u32(const void* p) {
    uint32_t a;
    asm("{ .reg .u64 t; cvta.to.shared.u64 t, %1; cvt.u32.u64 %0, t; }" : "=r"(a) : "l"(p));
    return a;
}
__device__ __forceinline__ uint32_t h2_bits(__half2 h) {
    return *(const uint32_t*)&h;
}

#define LDSM_X4(r, addr) \
    asm volatile("ldmatrix.sync.aligned.m8n8.x4.shared.b16 {%0,%1,%2,%3}, [%4];" \
        : "=r"((r)[0]), "=r"((r)[1]), "=r"((r)[2]), "=r"((r)[3]) : "r"(addr))

#define MMA16816(d, a, b0, b1) \
    asm volatile("mma.sync.aligned.m16n8k16.row.col.f32.f16.f16.f32 " \
        "{%0,%1,%2,%3}, {%4,%5,%6,%7}, {%8,%9}, {%0,%1,%2,%3};" \
        : "+f"((d)[0]), "+f"((d)[1]), "+f"((d)[2]), "+f"((d)[3]) \
        : "r"((a)[0]), "r"((a)[1]), "r"((a)[2]), "r"((a)[3]), "r"(b0), "r"(b1))

// ---------------- graph preprocessing ----------------
__global__ void k_init_deg() {
    int i = blockIdx.x * blockDim.x + threadIdx.x;
    if (i < NN) { g_deg_out[i] = 1; g_deg_in[i] = 1; }   // self-loop contributes 1
    if (i == 0) g_alloc = 0;
}

__global__ void k_count(const int* __restrict__ src, const int* __restrict__ dst) {
    int e = blockIdx.x * blockDim.x + threadIdx.x;
    if (e < NE) {
        atomicAdd(&g_deg_out[src[e]], 1);
        atomicAdd(&g_deg_in[dst[e]], 1);
    }
}

__global__ void k_norm_alloc() {
    int i = blockIdx.x * blockDim.x + threadIdx.x;
    int lane = threadIdx.x & 31;
    bool valid = i < NN;
    int din  = valid ? g_deg_in[i]  : 1;
    int dout = valid ? g_deg_out[i] : 1;
    if (valid) {
        g_norm_src[i] = rsqrtf((float)dout);
        g_norm_dst[i] = rsqrtf((float)din);
    }
    int d = din - 1;
    int p = d;
#pragma unroll
    for (int off = 1; off < 32; off <<= 1) {
        int v = __shfl_up_sync(0xffffffffu, p, off);
        if (lane >= off) p += v;
    }
    int total = __shfl_sync(0xffffffffu, p, 31);
    int base = 0;
    if (lane == 31) base = atomicAdd(&g_alloc, total);
    base = __shfl_sync(0xffffffffu, base, 31);
    int start = base + p - d;
    if (valid) { g_row_start[i] = start; g_cursor[i] = start; }
}

__global__ void k_fill(const int* __restrict__ src, const int* __restrict__ dst) {
    int e = blockIdx.x * blockDim.x + threadIdx.x;
    if (e < NE) {
        int p = atomicAdd(&g_cursor[dst[e]], 1);
        g_col[p] = src[e];
    }
}

// ---------------- W prep: W^T -> fp16 hi/lo, padded rows ----------------
__global__ void k_wprep(const float* __restrict__ Ws) {
    int idx = blockIdx.x * blockDim.x + threadIdx.x;
    if (idx >= 3 * D * D) return;
    int l = idx >> 14;
    int r = idx & 16383;
    int n = r >> 7;
    int k = r & 127;
    float v = Ws[(l << 14) + (k << 7) + n];          // W[l][k][n] = Wt[n][k]
    __half hi = __float2half_rn(v);
    __half lo = __float2half_rn(v - __half2float(hi));
    int o = (l * D + n) * PW + k;
    g_Whp[o] = hi;
    g_Wlp[o] = lo;
    if (k < PW - D) {                                // zero the pad
        g_Whp[(l * D + n) * PW + D + k] = __float2half_rn(0.f);
        g_Wlp[(l * D + n) * PW + D + k] = __float2half_rn(0.f);
    }
}

// ---------------- layer-0 input scale: g_hs = fp16(input * norm_src) ----------
__global__ void k_scale0(const float* __restrict__ in) {
    int idx = blockIdx.x * blockDim.x + threadIdx.x;   // float4 / half4 index
    if (idx < NN * (D / 4)) {
        int row = idx >> 5;
        float s = g_norm_src[row];
        float4 v = ((const float4*)in)[idx];
        __half2 h0 = __floats2half2_rn(v.x * s, v.y * s);
        __half2 h1 = __floats2half2_rn(v.z * s, v.w * s);
        ((uint2*)g_hs)[idx] = make_uint2(h2_bits(h0), h2_bits(h1));
    }
}

// ---------------- aggregation: warp per node; fp16 gather, f32 accumulate -----
// Each lane owns 4 columns (8B per row). Epilogue emits fp16 hi/lo GEMM input.
__global__ __launch_bounds__(256) void k_agg() {
    int gw   = (blockIdx.x * blockDim.x + threadIdx.x) >> 5;
    int lane = threadIdx.x & 31;
    if (gw >= NN) return;
    const uint2* __restrict__ h2 = (const uint2*)g_hs;   // 4 halves per entry
    int base = gw * 32 + lane;

    float a0, a1, a2, a3;
    {
        uint2 v = h2[base];                 // self-loop term
        float2 f0 = __half22float2(*(const __half2*)&v.x);
        float2 f1 = __half22float2(*(const __half2*)&v.y);
        a0 = f0.x; a1 = f0.y; a2 = f1.x; a3 = f1.y;
    }
    int s = g_row_start[gw];
    int e = s + g_deg_in[gw] - 1;
    int i = s;
    for (; i + 4 <= e; i += 4) {
        int c0 = g_col[i], c1 = g_col[i + 1], c2 = g_col[i + 2], c3 = g_col[i + 3];
        uint2 v0 = h2[c0 * 32 + lane];
        uint2 v1 = h2[c1 * 32 + lane];
        uint2 v2 = h2[c2 * 32 + lane];
        uint2 v3 = h2[c3 * 32 + lane];
        float2 p00 = __half22float2(*(const __half2*)&v0.x), p01 = __half22float2(*(const __half2*)&v0.y);
        float2 p10 = __half22float2(*(const __half2*)&v1.x), p11 = __half22float2(*(const __half2*)&v1.y);
        float2 p20 = __half22float2(*(const __half2*)&v2.x), p21 = __half22float2(*(const __half2*)&v2.y);
        float2 p30 = __half22float2(*(const __half2*)&v3.x), p31 = __half22float2(*(const __half2*)&v3.y);
        a0 += (p00.x + p10.x) + (p20.x + p30.x);
        a1 += (p00.y + p10.y) + (p20.y + p30.y);
        a2 += (p01.x + p11.x) + (p21.x + p31.x);
        a3 += (p01.y + p11.y) + (p21.y + p31.y);
    }
    for (; i < e; i++) {
        int c = g_col[i];
        uint2 v = h2[c * 32 + lane];
        float2 f0 = __half22float2(*(const __half2*)&v.x);
        float2 f1 = __half22float2(*(const __half2*)&v.y);
        a0 += f0.x; a1 += f0.y; a2 += f1.x; a3 += f1.y;
    }
    float nd = g_norm_dst[gw];             // fold norm_dst here
    float av[4] = { a0 * nd, a1 * nd, a2 * nd, a3 * nd };

    // fp16 hi/lo split (3-term GEMM input)
    __half hh[4], ll[4];
#pragma unroll
    for (int j = 0; j < 4; j++) {
        hh[j] = __float2half_rn(av[j]);
        ll[j] = __float2half_rn(av[j] - __half2float(hh[j]));
    }
    *(uint2*)(&g_Ah[gw * D + 4 * lane]) = *(const uint2*)hh;
    *(uint2*)(&g_Al[gw * D + 4 * lane]) = *(const uint2*)ll;
}

// ---------------- HMMA GEMM: h = A @ W + b (persistent) -----------------------
// Block 256 thr (8 warps): warp (wm,wc) owns 32 rows x 64 cols of a 128x128 tile.
// B (W^T hi/lo) staged in padded smem, fragments via ldmatrix.x4 (conflict-free);
// A fragments loaded directly from gmem (L2-resident). 3-term fp16 MMA.
// Layers 0/1: write fp16 relu(x)*norm_src into g_hs. Layer 2: f32 out.
__global__ __launch_bounds__(256, 2) void k_gemm_mma(
    int layer, const float* __restrict__ bias,
    int relu_scale, float* __restrict__ fout)
{
    extern __shared__ __half sm[];              // [2][128*136] halves
    __shared__ float s_bias[D];

    int tid  = threadIdx.x;
    int wid  = tid >> 5;
    int lane = tid & 31;
    int wm   = wid & 3;        // row 32-group
    int wc   = wid >> 2;       // col 64-half
    int q    = lane & 3;
    int tr   = lane >> 2;

    // stage W^T hi/lo (padded layout identical in gmem -> bulk int4 copy)
    {
        const int4* srcH = (const int4*)(g_Whp + layer * D * PW);
        const int4* srcL = (const int4*)(g_Wlp + layer * D * PW);
        int4* dstH = (int4*)sm;
        int4* dstL = (int4*)(sm + D * PW);
        const int CH = D * PW * 2 / 16;   // 2176 int4 per array
        for (int i = tid; i < CH; i += 256) { dstH[i] = srcH[i]; dstL[i] = srcL[i]; }
    }
    if (tid < D) s_bias[tid] = bias[tid];
    __syncthreads();

    uint32_t sH = smem_u32(sm);
    uint32_t sL = sH + D * PW * 2;
    // ldmatrix per-thread row address (byte): matrix id m = lane/8, row r = lane%8
    int lm_m = lane >> 3;
    int lm_r = lane & 7;
    uint32_t lm_off = (uint32_t)(8 * (lm_m >> 1) + lm_r) * (PW * 2) + (uint32_t)(lm_m & 1) * 16;

    const __half* __restrict__ Ah = g_Ah;
    const __half* __restrict__ Al = g_Al;

    for (int t = blockIdx.x; t < NTILES; t += gridDim.x) {
        int r0 = t * 128;
        bool full = (r0 + 128 <= NN);
        int rbase0 = r0 + wm * 32 + tr;       // mset 0 rows: rbase0, rbase0+8
        int rbase1 = rbase0 + 16;             // mset 1 rows: rbase1, rbase1+8

        float acc[2][8][4];
#pragma unroll
        for (int m = 0; m < 2; m++)
#pragma unroll
            for (int j = 0; j < 8; j++)
#pragma unroll
                for (int c = 0; c < 4; c++) acc[m][j][c] = 0.f;

        for (int s = 0; s < 8; s++) {
            int kb = s * 16 + q * 2;          // element offset within row
            uint32_t aH[2][4], aL[2][4];
#pragma unroll
            for (int m = 0; m < 2; m++) {
                int ra = (m ? rbase1 : rbase0);
                int rb = ra + 8;
                size_t oa = (size_t)ra * D + kb;
                size_t ob = (size_t)rb * D + kb;
                if (full || rb < NN) {
                    aH[m][0] = *(const uint32_t*)(Ah + oa);
                    aH[m][2] = *(const uint32_t*)(Ah + oa + 8);
                    aH[m][1] = *(const uint32_t*)(Ah + ob);
                    aH[m][3] = *(const uint32_t*)(Ah + ob + 8);
                    aL[m][0] = *(const uint32_t*)(Al + oa);
                    aL[m][2] = *(const uint32_t*)(Al + oa + 8);
                    aL[m][1] = *(const uint32_t*)(Al + ob);
                    aL[m][3] = *(const uint32_t*)(Al + ob + 8);
                } else {
                    bool va = ra < NN;
                    aH[m][0] = va ? *(const uint32_t*)(Ah + oa) : 0u;
                    aH[m][2] = va ? *(const uint32_t*)(Ah + oa + 8) : 0u;
                    aL[m][0] = va ? *(const uint32_t*)(Al + oa) : 0u;
                    aL[m][2] = va ? *(const uint32_t*)(Al + oa + 8) : 0u;
                    aH[m][1] = 0u; aH[m][3] = 0u; aL[m][1] = 0u; aL[m][3] = 0u;
                }
            }
#pragma unroll
            for (int p = 0; p < 4; p++) {     // ntile pairs (j = 2p, 2p+1)
                uint32_t nb = (uint32_t)(wc * 64 + p * 16) * (PW * 2) + (uint32_t)s * 32;
                uint32_t bH[4], bL[4];
                LDSM_X4(bH, sH + nb + lm_off);
                LDSM_X4(bL, sL + nb + lm_off);
#pragma unroll
                for (int m = 0; m < 2; m++) {
#pragma unroll
                    for (int u = 0; u < 2; u++) {
                        int j = 2 * p + u;
                        MMA16816(acc[m][j], aH[m], bH[2 * u], bH[2 * u + 1]);   // Ah*Bh
                        MMA16816(acc[m][j], aH[m], bL[2 * u], bL[2 * u + 1]);   // Ah*Bl
                        MMA16816(acc[m][j], aL[m], bH[2 * u], bH[2 * u + 1]);   // Al*Bh
                    }
                }
            }
        }

        // epilogue: bias + (relu * norm_src) fused; c0,c1 -> row, c2,c3 -> row+8
#pragma unroll
        for (int m = 0; m < 2; m++) {
            int ra = (m ? rbase1 : rbase0);
            int rb = ra + 8;
            float nsa = 1.f, nsb = 1.f;
            if (relu_scale) {
                if (ra < NN) nsa = g_norm_src[ra];
                if (rb < NN) nsb = g_norm_src[rb];
            }
#pragma unroll
            for (int j = 0; j < 8; j++) {
                int col = wc * 64 + j * 8 + q * 2;
                float b0 = s_bias[col], b1 = s_bias[col + 1];
                float v0 = acc[m][j][0] + b0, v1 = acc[m][j][1] + b1;
                float v2 = acc[m][j][2] + b0, v3 = acc[m][j][3] + b1;
                if (relu_scale) {
                    // relu(x)*s == relu(x*s), s>0; store fp16 gather source
                    v0 = fmaxf(v0, 0.f) * nsa; v1 = fmaxf(v1, 0.f) * nsa;
                    v2 = fmaxf(v2, 0.f) * nsb; v3 = fmaxf(v3, 0.f) * nsb;
                    if (ra < NN) {
                        __half2 h = __floats2half2_rn(v0, v1);
                        *(uint32_t*)(&g_hs[(size_t)ra * D + col]) = h2_bits(h);
                    }
                    if (rb < NN) {
                        __half2 h = __floats2half2_rn(v2, v3);
                        *(uint32_t*)(&g_hs[(size_t)rb * D + col]) = h2_bits(h);
                    }
                } else {
                    if (ra < NN) *(float2*)(fout + (size_t)ra * D + col) = make_float2(v0, v1);
                    if (rb < NN) *(float2*)(fout + (size_t)rb * D + col) = make_float2(v2, v3);
                }
            }
        }
    }
}

// ---------------- launch ----------------
extern "C" void kernel_launch(void* const* d_in, const int* in_sizes, int n_in,
                              void* d_out, int out_size) {
    const float* inputs = (const float*)d_in[0];   // [N,128]
    const float* Ws     = (const float*)d_in[1];   // [3,128,128]
    const float* bs     = (const float*)d_in[2];   // [3,128]
    const int*   src    = (const int*)d_in[3];     // [E]
    const int*   dst    = (const int*)d_in[4];     // [E]
    float*       out    = (float*)d_out;           // [N,128]

    const int gemm_smem = 2 * D * PW * (int)sizeof(__half);   // 69632
    cudaFuncSetAttribute(k_gemm_mma, cudaFuncAttributeMaxDynamicSharedMemorySize, gemm_smem);

    // graph preprocessing (every call; int atomics only)
    k_init_deg<<<(NN + 255) / 256, 256>>>();
    k_count<<<(NE + 255) / 256, 256>>>(src, dst);
    k_norm_alloc<<<(NN + 255) / 256, 256>>>();
    k_fill<<<(NE + 255) / 256, 256>>>(src, dst);

    // W split + layer-0 input scale (fp16 gather source)
    k_wprep<<<(3 * D * D + 255) / 256, 256>>>(Ws);
    k_scale0<<<(NN * (D / 4) + 255) / 256, 256>>>(inputs);

    const int agg_blocks = (NN * 32 + 255) / 256;   // warp per node

    for (int l = 0; l < 3; l++) {
        k_agg<<<agg_blocks, 256>>>();
        k_gemm_mma<<<296, 256, gemm_smem>>>(
            l, bs + l * D,
            (l < 2) ? 1 : 0,
            (l == 2) ? out : nullptr);
    }
}

// round 15
// speedup vs baseline: 2.3075x; 1.0175x over previous
#include <cuda_runtime.h>
#include <cuda_fp16.h>
#include <cstdint>

#define NN 100000
#define NE 1600000
#define D  128
#define NTILES ((NN + 127) / 128)   // 782
#define PW 136                       // padded row (halves): 272B -> conflict-free ldmatrix
#define DP (D * PW)                  // halves per 128-row padded array

// ---------------- scratch (device globals; allocation-free) ----------------
__device__ __half g_hs[NN * D];       // gather source: h * norm_src, fp16
__device__ __half g_Ah[NN * D];       // gemm input (aggregated), fp16 hi
__device__ __half g_Al[NN * D];       // gemm input (aggregated), fp16 lo
__device__ float  g_norm_src[NN];
__device__ float  g_norm_dst[NN];
__device__ int    g_deg_out[NN];
__device__ int    g_deg_in[NN];
__device__ int    g_row_start[NN];
__device__ int    g_cursor[NN];
__device__ int    g_col[NE];
__device__ int    g_alloc;
__device__ __half g_Whp[3 * DP];      // W^T fp16-hi, padded rows
__device__ __half g_Wlp[3 * DP];      // W^T fp16-lo, padded rows

// ---------------- helpers ----------------
__device__ __forceinline__ uint32_t smem_u32(const void* p) {
    uint32_t a;
    asm("{ .reg .u64 t; cvta.to.shared.u64 t, %1; cvt.u32.u64 %0, t; }" : "=r"(a) : "l"(p));
    return a;
}
__device__ __forceinline__ uint32_t h2_bits(__half2 h) {
    return *(const uint32_t*)&h;
}

#define LDSM_X4(r, addr) \
    asm volatile("ldmatrix.sync.aligned.m8n8.x4.shared.b16 {%0,%1,%2,%3}, [%4];" \
        : "=r"((r)[0]), "=r"((r)[1]), "=r"((r)[2]), "=r"((r)[3]) : "r"(addr))

#define MMA16816(d, a, b0, b1) \
    asm volatile("mma.sync.aligned.m16n8k16.row.col.f32.f16.f16.f32 " \
        "{%0,%1,%2,%3}, {%4,%5,%6,%7}, {%8,%9}, {%0,%1,%2,%3};" \
        : "+f"((d)[0]), "+f"((d)[1]), "+f"((d)[2]), "+f"((d)[3]) \
        : "r"((a)[0]), "r"((a)[1]), "r"((a)[2]), "r"((a)[3]), "r"(b0), "r"(b1))

// ---------------- graph preprocessing ----------------
__global__ void k_init_deg() {
    int i = blockIdx.x * blockDim.x + threadIdx.x;
    if (i < NN) { g_deg_out[i] = 1; g_deg_in[i] = 1; }   // self-loop contributes 1
    if (i == 0) g_alloc = 0;
}

__global__ void k_count(const int* __restrict__ src, const int* __restrict__ dst) {
    int e = blockIdx.x * blockDim.x + threadIdx.x;
    if (e < NE) {
        atomicAdd(&g_deg_out[src[e]], 1);
        atomicAdd(&g_deg_in[dst[e]], 1);
    }
}

__global__ void k_norm_alloc() {
    int i = blockIdx.x * blockDim.x + threadIdx.x;
    int lane = threadIdx.x & 31;
    bool valid = i < NN;
    int din  = valid ? g_deg_in[i]  : 1;
    int dout = valid ? g_deg_out[i] : 1;
    if (valid) {
        g_norm_src[i] = rsqrtf((float)dout);
        g_norm_dst[i] = rsqrtf((float)din);
    }
    int d = din - 1;
    int p = d;
#pragma unroll
    for (int off = 1; off < 32; off <<= 1) {
        int v = __shfl_up_sync(0xffffffffu, p, off);
        if (lane >= off) p += v;
    }
    int total = __shfl_sync(0xffffffffu, p, 31);
    int base = 0;
    if (lane == 31) base = atomicAdd(&g_alloc, total);
    base = __shfl_sync(0xffffffffu, base, 31);
    int start = base + p - d;
    if (valid) { g_row_start[i] = start; g_cursor[i] = start; }
}

__global__ void k_fill(const int* __restrict__ src, const int* __restrict__ dst) {
    int e = blockIdx.x * blockDim.x + threadIdx.x;
    if (e < NE) {
        int p = atomicAdd(&g_cursor[dst[e]], 1);
        g_col[p] = src[e];
    }
}

// ---------------- W prep: W^T -> fp16 hi/lo, padded rows ----------------
__global__ void k_wprep(const float* __restrict__ Ws) {
    int idx = blockIdx.x * blockDim.x + threadIdx.x;
    if (idx >= 3 * D * D) return;
    int l = idx >> 14;
    int r = idx & 16383;
    int n = r >> 7;
    int k = r & 127;
    float v = Ws[(l << 14) + (k << 7) + n];          // W[l][k][n] = Wt[n][k]
    __half hi = __float2half_rn(v);
    __half lo = __float2half_rn(v - __half2float(hi));
    int o = l * DP + n * PW + k;
    g_Whp[o] = hi;
    g_Wlp[o] = lo;
    if (k < PW - D) {                                // zero the pad
        g_Whp[l * DP + n * PW + D + k] = __float2half_rn(0.f);
        g_Wlp[l * DP + n * PW + D + k] = __float2half_rn(0.f);
    }
}

// ---------------- layer-0 input scale: g_hs = fp16(input * norm_src) ----------
__global__ void k_scale0(const float* __restrict__ in) {
    int idx = blockIdx.x * blockDim.x + threadIdx.x;   // float4 / half4 index
    if (idx < NN * (D / 4)) {
        int row = idx >> 5;
        float s = g_norm_src[row];
        float4 v = ((const float4*)in)[idx];
        __half2 h0 = __floats2half2_rn(v.x * s, v.y * s);
        __half2 h1 = __floats2half2_rn(v.z * s, v.w * s);
        ((uint2*)g_hs)[idx] = make_uint2(h2_bits(h0), h2_bits(h1));
    }
}

// ---------------- aggregation: warp per node; fp16 gather, f32 accumulate -----
__global__ __launch_bounds__(256) void k_agg() {
    int gw   = (blockIdx.x * blockDim.x + threadIdx.x) >> 5;
    int lane = threadIdx.x & 31;
    if (gw >= NN) return;
    const uint2* __restrict__ h2 = (const uint2*)g_hs;   // 4 halves per entry
    int base = gw * 32 + lane;

    float a0, a1, a2, a3;
    {
        uint2 v = h2[base];                 // self-loop term
        float2 f0 = __half22float2(*(const __half2*)&v.x);
        float2 f1 = __half22float2(*(const __half2*)&v.y);
        a0 = f0.x; a1 = f0.y; a2 = f1.x; a3 = f1.y;
    }
    int s = g_row_start[gw];
    int e = s + g_deg_in[gw] - 1;
    int i = s;
    for (; i + 4 <= e; i += 4) {
        int c0 = g_col[i], c1 = g_col[i + 1], c2 = g_col[i + 2], c3 = g_col[i + 3];
        uint2 v0 = h2[c0 * 32 + lane];
        uint2 v1 = h2[c1 * 32 + lane];
        uint2 v2 = h2[c2 * 32 + lane];
        uint2 v3 = h2[c3 * 32 + lane];
        float2 p00 = __half22float2(*(const __half2*)&v0.x), p01 = __half22float2(*(const __half2*)&v0.y);
        float2 p10 = __half22float2(*(const __half2*)&v1.x), p11 = __half22float2(*(const __half2*)&v1.y);
        float2 p20 = __half22float2(*(const __half2*)&v2.x), p21 = __half22float2(*(const __half2*)&v2.y);
        float2 p30 = __half22float2(*(const __half2*)&v3.x), p31 = __half22float2(*(const __half2*)&v3.y);
        a0 += (p00.x + p10.x) + (p20.x + p30.x);
        a1 += (p00.y + p10.y) + (p20.y + p30.y);
        a2 += (p01.x + p11.x) + (p21.x + p31.x);
        a3 += (p01.y + p11.y) + (p21.y + p31.y);
    }
    for (; i < e; i++) {
        int c = g_col[i];
        uint2 v = h2[c * 32 + lane];
        float2 f0 = __half22float2(*(const __half2*)&v.x);
        float2 f1 = __half22float2(*(const __half2*)&v.y);
        a0 += f0.x; a1 += f0.y; a2 += f1.x; a3 += f1.y;
    }
    float nd = g_norm_dst[gw];             // fold norm_dst here
    float av[4] = { a0 * nd, a1 * nd, a2 * nd, a3 * nd };

    __half hh[4], ll[4];
#pragma unroll
    for (int j = 0; j < 4; j++) {
        hh[j] = __float2half_rn(av[j]);
        ll[j] = __float2half_rn(av[j] - __half2float(hh[j]));
    }
    *(uint2*)(&g_Ah[gw * D + 4 * lane]) = *(const uint2*)hh;
    *(uint2*)(&g_Al[gw * D + 4 * lane]) = *(const uint2*)ll;
}

// ---------------- HMMA GEMM: h = A @ W + b (persistent, all-smem operands) ----
// smem: W_h | W_l | A_h | A_l, all 128x128 padded to 136-half rows (139KB).
// Warp (wm,wc) owns 32 rows x 64 cols. A and B fragments both via ldmatrix.x4
// (conflict-free, stride 272B). Mainloop: 12 LDSM + 48 MMA per k-step per warp.
__global__ __launch_bounds__(256, 1) void k_gemm_mma(
    int layer, const float* __restrict__ bias,
    int relu_scale, float* __restrict__ fout)
{
    extern __shared__ __half sm[];              // [4][DP]
    __shared__ float s_bias[D];

    int tid  = threadIdx.x;
    int wid  = tid >> 5;
    int lane = tid & 31;
    int wm   = wid & 3;        // row 32-group
    int wc   = wid >> 2;       // col 64-half
    int q    = lane & 3;
    int tr   = lane >> 2;

    // stage W^T hi/lo once (padded layout identical in gmem -> bulk int4 copy)
    {
        const int4* srcH = (const int4*)(g_Whp + layer * DP);
        const int4* srcL = (const int4*)(g_Wlp + layer * DP);
        int4* dstH = (int4*)sm;
        int4* dstL = (int4*)(sm + DP);
        const int CH = DP * 2 / 16;   // 2176 int4 per array
        for (int i = tid; i < CH; i += 256) { dstH[i] = srcH[i]; dstL[i] = srcL[i]; }
    }
    if (tid < D) s_bias[tid] = bias[tid];

    uint32_t sWH = smem_u32(sm);
    uint32_t sWL = sWH + DP * 2;
    uint32_t sAH = sWH + 2 * DP * 2;
    uint32_t sAL = sWH + 3 * DP * 2;

    int lm_m = lane >> 3;
    int lm_r = lane & 7;
    // B (n-major rows): row-block from m>>1, k-halfblock from m&1
    uint32_t b_lm = (uint32_t)(8 * (lm_m >> 1) + lm_r) * (PW * 2) + (uint32_t)(lm_m & 1) * 16;
    // A (row-major): row from m&1, k-halfblock from m>>1
    uint32_t a_lm = (uint32_t)(8 * (lm_m & 1) + lm_r) * (PW * 2) + (uint32_t)(lm_m >> 1) * 16;

    for (int t = blockIdx.x; t < NTILES; t += gridDim.x) {
        int r0 = t * 128;

        // stage A tile hi/lo: 128 rows x 16 int4 (256B payload) -> padded rows
        {
            const int4* srcH = (const int4*)(g_Ah + (size_t)r0 * D);
            const int4* srcL = (const int4*)(g_Al + (size_t)r0 * D);
            int4* dstH = (int4*)(sm + 2 * DP);
            int4* dstL = (int4*)(sm + 3 * DP);
            const int4 z = make_int4(0, 0, 0, 0);
#pragma unroll
            for (int i = 0; i < 8; i++) {
                int idx = tid + i * 256;        // 0..2047
                int r = idx >> 4;
                int c = idx & 15;
                bool v = (r0 + r) < NN;
                int gidx = r * 16 + c;          // int4 index in row-major source
                dstH[r * 17 + c] = v ? srcH[gidx] : z;
                dstL[r * 17 + c] = v ? srcL[gidx] : z;
            }
        }
        __syncthreads();

        float acc[2][8][4];
#pragma unroll
        for (int m = 0; m < 2; m++)
#pragma unroll
            for (int j = 0; j < 8; j++)
#pragma unroll
                for (int c = 0; c < 4; c++) acc[m][j][c] = 0.f;

#pragma unroll
        for (int s = 0; s < 8; s++) {
            uint32_t aH[2][4], aL[2][4];
#pragma unroll
            for (int m = 0; m < 2; m++) {
                uint32_t ab = (uint32_t)(wm * 32 + m * 16) * (PW * 2) + (uint32_t)s * 32 + a_lm;
                LDSM_X4(aH[m], sAH + ab);
                LDSM_X4(aL[m], sAL + ab);
            }
#pragma unroll
            for (int p = 0; p < 4; p++) {     // ntile pairs (j = 2p, 2p+1)
                uint32_t nb = (uint32_t)(wc * 64 + p * 16) * (PW * 2) + (uint32_t)s * 32;
                uint32_t bH[4], bL[4];
                LDSM_X4(bH, sWH + nb + b_lm);
                LDSM_X4(bL, sWL + nb + b_lm);
#pragma unroll
                for (int m = 0; m < 2; m++) {
#pragma unroll
                    for (int u = 0; u < 2; u++) {
                        int j = 2 * p + u;
                        MMA16816(acc[m][j], aH[m], bH[2 * u], bH[2 * u + 1]);   // Ah*Bh
                        MMA16816(acc[m][j], aH[m], bL[2 * u], bL[2 * u + 1]);   // Ah*Bl
                        MMA16816(acc[m][j], aL[m], bH[2 * u], bH[2 * u + 1]);   // Al*Bh
                    }
                }
            }
        }

        // epilogue: bias + (relu * norm_src) fused; c0,c1 -> row, c2,c3 -> row+8
#pragma unroll
        for (int m = 0; m < 2; m++) {
            int ra = r0 + wm * 32 + m * 16 + tr;
            int rb = ra + 8;
            float nsa = 1.f, nsb = 1.f;
            if (relu_scale) {
                if (ra < NN) nsa = g_norm_src[ra];
                if (rb < NN) nsb = g_norm_src[rb];
            }
#pragma unroll
            for (int j = 0; j < 8; j++) {
                int col = wc * 64 + j * 8 + q * 2;
                float b0 = s_bias[col], b1 = s_bias[col + 1];
                float v0 = acc[m][j][0] + b0, v1 = acc[m][j][1] + b1;
                float v2 = acc[m][j][2] + b0, v3 = acc[m][j][3] + b1;
                if (relu_scale) {
                    // relu(x)*s == relu(x*s), s>0; store fp16 gather source
                    v0 = fmaxf(v0, 0.f) * nsa; v1 = fmaxf(v1, 0.f) * nsa;
                    v2 = fmaxf(v2, 0.f) * nsb; v3 = fmaxf(v3, 0.f) * nsb;
                    if (ra < NN) {
                        __half2 h = __floats2half2_rn(v0, v1);
                        *(uint32_t*)(&g_hs[(size_t)ra * D + col]) = h2_bits(h);
                    }
                    if (rb < NN) {
                        __half2 h = __floats2half2_rn(v2, v3);
                        *(uint32_t*)(&g_hs[(size_t)rb * D + col]) = h2_bits(h);
                    }
                } else {
                    if (ra < NN) *(float2*)(fout + (size_t)ra * D + col) = make_float2(v0, v1);
                    if (rb < NN) *(float2*)(fout + (size_t)rb * D + col) = make_float2(v2, v3);
                }
            }
        }
        __syncthreads();   // A buffer reuse barrier
    }
}

// ---------------- launch ----------------
extern "C" void kernel_launch(void* const* d_in, const int* in_sizes, int n_in,
                              void* d_out, int out_size) {
    const float* inputs = (const float*)d_in[0];   // [N,128]
    const float* Ws     = (const float*)d_in[1];   // [3,128,128]
    const float* bs     = (const float*)d_in[2];   // [3,128]
    const int*   src    = (const int*)d_in[3];     // [E]
    const int*   dst    = (const int*)d_in[4];     // [E]
    float*       out    = (float*)d_out;           // [N,128]

    const int gemm_smem = 4 * DP * (int)sizeof(__half);   // 139264
    cudaFuncSetAttribute(k_gemm_mma, cudaFuncAttributeMaxDynamicSharedMemorySize, gemm_smem);

    // graph preprocessing (every call; int atomics only)
    k_init_deg<<<(NN + 255) / 256, 256>>>();
    k_count<<<(NE + 255) / 256, 256>>>(src, dst);
    k_norm_alloc<<<(NN + 255) / 256, 256>>>();
    k_fill<<<(NE + 255) / 256, 256>>>(src, dst);

    // W split + layer-0 input scale (fp16 gather source)
    k_wprep<<<(3 * D * D + 255) / 256, 256>>>(Ws);
    k_scale0<<<(NN * (D / 4) + 255) / 256, 256>>>(inputs);

    const int agg_blocks = (NN * 32 + 255) / 256;   // warp per node

    for (int l = 0; l < 3; l++) {
        k_agg<<<agg_blocks, 256>>>();
        k_gemm_mma<<<148, 256, gemm_smem>>>(
            l, bs + l * D,
            (l < 2) ? 1 : 0,
            (l == 2) ? out : nullptr);
    }
}